// round 1
// baseline (speedup 1.0000x reference)
#include <cuda_runtime.h>
#include <math.h>

// Problem constants
#define Bn    64
#define Sn    256
#define En    256
#define Hn    256          // per-direction hidden
#define Gn    1024         // 4*Hn
#define Tn    32
#define NTOK  (Bn*Sn)      // 16384

// ---------------- scratch (static device globals; no allocation) ----------------
__device__ float g_x[NTOK*En];                 // x[s][b][e], m = s*64+b       (16 MB)
__device__ float g_zx[2u*NTOK*Gn];             // Zx[dir][m][1024]             (128 MB)
__device__ float g_h[2*2*Bn*Hn];               // h[parity][dir][b][j]
__device__ float g_hseq[2u*Bn*Sn*Hn];          // hseq[dir][b][t][j]           (32 MB)
__device__ float g_feats[NTOK*Tn];             // feats[b][s][tag]             (2 MB)
__device__ unsigned g_bar_count;               // grid barrier (sense-reversing)
__device__ unsigned g_bar_gen;

// ---------------- 1) embedding gather: x[s][b][:] = embed[sentence[b][s]] ------
__global__ void k_embed(const int* __restrict__ sent, const float* __restrict__ emb)
{
    int idx = blockIdx.x * 256 + threadIdx.x;    // one token per block (e = tid)
    int e = idx & 255;
    int m = idx >> 8;            // s*64+b
    int b = m & 63, s = m >> 6;
    int w = sent[b * Sn + s];
    g_x[idx] = emb[(size_t)w * En + e];
}

// ---------------- 2) Zx GEMM: C[m][n] = sum_k X[m][k]*W[n][k] + bias[n] --------
// X: [16384,256] row-major, W: [1024,256] row-major (NT gemm). 128x128 tile, 8x8 micro.
__global__ __launch_bounds__(256, 2)
void k_gemm(const float* __restrict__ W, const float* __restrict__ bias, int dir)
{
    __shared__ float As[16][128];
    __shared__ float Bs[16][128];

    const int tid  = threadIdx.x;
    const int bm   = blockIdx.x << 7;
    const int bn   = blockIdx.y << 7;
    const int warp = tid >> 5, lane = tid & 31;
    const int tm   = ((warp & 3) << 5) + ((lane >> 3) << 3);   // m offset in tile
    const int tn   = ((warp >> 2) << 6) + ((lane & 7) << 3);   // n offset in tile
    const int lr   = tid >> 2;          // 0..63 (rows for loading)
    const int lc   = tid & 3;           // float4 index within BK=16

    float acc[8][8];
#pragma unroll
    for (int i = 0; i < 8; i++)
#pragma unroll
        for (int j = 0; j < 8; j++) acc[i][j] = 0.f;

    for (int k0 = 0; k0 < En; k0 += 16) {
#pragma unroll
        for (int r = 0; r < 2; r++) {
            int mrow = bm + lr + (r << 6);
            float4 v = *(const float4*)(g_x + (size_t)mrow * En + k0 + (lc << 2));
            As[(lc << 2) + 0][lr + (r << 6)] = v.x;
            As[(lc << 2) + 1][lr + (r << 6)] = v.y;
            As[(lc << 2) + 2][lr + (r << 6)] = v.z;
            As[(lc << 2) + 3][lr + (r << 6)] = v.w;
            int nrow = bn + lr + (r << 6);
            float4 wv = *(const float4*)(W + (size_t)nrow * En + k0 + (lc << 2));
            Bs[(lc << 2) + 0][lr + (r << 6)] = wv.x;
            Bs[(lc << 2) + 1][lr + (r << 6)] = wv.y;
            Bs[(lc << 2) + 2][lr + (r << 6)] = wv.z;
            Bs[(lc << 2) + 3][lr + (r << 6)] = wv.w;
        }
        __syncthreads();
#pragma unroll
        for (int kk = 0; kk < 16; kk++) {
            float a[8], bb[8];
            *(float4*)(a)      = *(const float4*)&As[kk][tm];
            *(float4*)(a + 4)  = *(const float4*)&As[kk][tm + 4];
            *(float4*)(bb)     = *(const float4*)&Bs[kk][tn];
            *(float4*)(bb + 4) = *(const float4*)&Bs[kk][tn + 4];
#pragma unroll
            for (int i = 0; i < 8; i++)
#pragma unroll
                for (int j = 0; j < 8; j++)
                    acc[i][j] += a[i] * bb[j];
        }
        __syncthreads();
    }

    float bv[8];
#pragma unroll
    for (int j = 0; j < 8; j++) bv[j] = bias[bn + tn + j];

    float* C = g_zx + (size_t)dir * NTOK * Gn;
#pragma unroll
    for (int i = 0; i < 8; i++) {
        size_t off = (size_t)(bm + tm + i) * Gn + bn + tn;
        float4 o0 = make_float4(acc[i][0] + bv[0], acc[i][1] + bv[1],
                                acc[i][2] + bv[2], acc[i][3] + bv[3]);
        float4 o1 = make_float4(acc[i][4] + bv[4], acc[i][5] + bv[5],
                                acc[i][6] + bv[6], acc[i][7] + bv[7]);
        *(float4*)(C + off)     = o0;
        *(float4*)(C + off + 4) = o1;
    }
}

// ---------------- 3) persistent bidirectional LSTM (128 blocks, grid barrier) --
// block = (dir, 4 hidden units). Whh slice resident in smem for all 256 steps.
// thread: b = tid>>2 (64 batches), jj = tid&3 (unit within slice). c in register.
#define WS_STRIDE 264          // padded row for W slice (bank spread over jj)
#define HS_STRIDE 260          // padded row for staged h (bank spread over b)
#define SMEM_LSTM ((4*4*WS_STRIDE + Bn*HS_STRIDE) * sizeof(float))

__global__ __launch_bounds__(256)
void k_lstm(const float* __restrict__ Whh_f, const float* __restrict__ Whh_b)
{
    extern __shared__ float smx[];
    float* Ws = smx;                      // [4 gates][4 jj][WS_STRIDE]
    float* hs = smx + 4 * 4 * WS_STRIDE;  // [64 b][HS_STRIDE]

    const int tid = threadIdx.x;
    const int dir = blockIdx.x >> 6;
    const int j0  = (blockIdx.x & 63) << 2;
    const int b   = tid >> 2;
    const int jj  = tid & 3;

    const float* Whh = dir ? Whh_b : Whh_f;
    for (int idx = tid; idx < 4096; idx += 256) {
        int g = idx >> 10, rem = idx & 1023, j2 = rem >> 8, k = rem & 255;
        Ws[(g * 4 + j2) * WS_STRIDE + k] = Whh[(g * Hn + j0 + j2) * Hn + k];
    }

    // zero h(parity 0) for this block's slice
    g_h[(0 * 2 + dir) * (Bn * Hn) + b * Hn + j0 + jj] = 0.f;

    float c = 0.f;
    volatile unsigned* vgen = &g_bar_gen;
    unsigned gen = *vgen;                  // safe: no barrier of this launch can
                                           // complete before this block arrives
#define GRID_BAR() do {                                                   \
        __syncthreads();                                                  \
        if (tid == 0) {                                                   \
            __threadfence();                                              \
            unsigned tgt = ++gen;                                         \
            if (atomicAdd(&g_bar_count, 1u) == 127u) {                    \
                g_bar_count = 0u;                                         \
                __threadfence();                                          \
                atomicAdd(&g_bar_gen, 1u);                                \
            } else {                                                      \
                while (*vgen != tgt) { }                                  \
                __threadfence();                                          \
            }                                                             \
        }                                                                 \
        __syncthreads();                                                  \
    } while (0)

    GRID_BAR();   // h0 visible everywhere

    const size_t zdir = (size_t)dir * NTOK * Gn;
    const float* w0 = Ws + (0 * 4 + jj) * WS_STRIDE;
    const float* w1 = Ws + (1 * 4 + jj) * WS_STRIDE;
    const float* w2 = Ws + (2 * 4 + jj) * WS_STRIDE;
    const float* w3 = Ws + (3 * 4 + jj) * WS_STRIDE;
    const float* hr = hs + b * HS_STRIDE;

    for (int st = 0; st < Sn; ++st) {
        const int t   = dir ? (Sn - 1 - st) : st;
        const int par = st & 1;

        // stage h[par][dir] (64KB) into smem
        const float4* hp = (const float4*)(g_h + (par * 2 + dir) * (Bn * Hn));
#pragma unroll
        for (int i = 0; i < 16; i++) {
            int li = tid + (i << 8);
            float4 v = hp[li];
            int bb = li >> 6, kk = li & 63;
            *(float4*)(hs + bb * HS_STRIDE + (kk << 2)) = v;
        }
        __syncthreads();

        const float* zr = g_zx + zdir + ((size_t)(t * Bn + b) << 10) + j0 + jj;
        float z0 = zr[0], z1 = zr[256], z2 = zr[512], z3 = zr[768];

        float a0 = 0.f, a1 = 0.f, a2 = 0.f, a3 = 0.f;
#pragma unroll 8
        for (int k = 0; k < Hn; k += 4) {
            float4 hv = *(const float4*)(hr + k);
            float4 wv;
            wv = *(const float4*)(w0 + k);
            a0 += hv.x * wv.x + hv.y * wv.y + hv.z * wv.z + hv.w * wv.w;
            wv = *(const float4*)(w1 + k);
            a1 += hv.x * wv.x + hv.y * wv.y + hv.z * wv.z + hv.w * wv.w;
            wv = *(const float4*)(w2 + k);
            a2 += hv.x * wv.x + hv.y * wv.y + hv.z * wv.z + hv.w * wv.w;
            wv = *(const float4*)(w3 + k);
            a3 += hv.x * wv.x + hv.y * wv.y + hv.z * wv.z + hv.w * wv.w;
        }
        z0 += a0; z1 += a1; z2 += a2; z3 += a3;

        float ig = 1.f / (1.f + expf(-z0));
        float fg = 1.f / (1.f + expf(-z1));
        float gg = tanhf(z2);
        float og = 1.f / (1.f + expf(-z3));
        c = fg * c + ig * gg;
        float hn = og * tanhf(c);

        int j = j0 + jj;
        g_h[((par ^ 1) * 2 + dir) * (Bn * Hn) + b * Hn + j] = hn;
        g_hseq[(((size_t)dir * Bn + b) * Sn + t) * Hn + j] = hn;

        GRID_BAR();
    }
#undef GRID_BAR
}

// ---------------- 4) feats = concat(h_f,h_b) @ Wout^T + bout -------------------
// block: 8 tokens x 32 tags; Wout chunk staged transposed in smem.
__global__ __launch_bounds__(256)
void k_feats(const float* __restrict__ Wout, const float* __restrict__ bout)
{
    __shared__ float Wt[128][33];

    const int tid = threadIdx.x;
    const int tag = tid & 31;
    const int ti  = tid >> 5;                 // 0..7 token within block
    const int m   = blockIdx.x * 8 + ti;      // token id (s*64+b)
    const int bb  = m & 63, ss = m >> 6;

    float acc = bout[tag];

    for (int cch = 0; cch < 4; cch++) {       // k chunks of 128 (512 total)
        __syncthreads();
        for (int i = tid; i < 1024; i += 256) {
            int r = i >> 5;                   // tag row 0..31
            int k4 = i & 31;
            float4 w = *(const float4*)(Wout + (size_t)r * 512 + cch * 128 + (k4 << 2));
            Wt[(k4 << 2) + 0][r] = w.x;
            Wt[(k4 << 2) + 1][r] = w.y;
            Wt[(k4 << 2) + 2][r] = w.z;
            Wt[(k4 << 2) + 3][r] = w.w;
        }
        __syncthreads();

        const float* hrow;
        if (cch < 2)
            hrow = g_hseq + (((size_t)0 * Bn + bb) * Sn + ss) * Hn + cch * 128;
        else
            hrow = g_hseq + (((size_t)1 * Bn + bb) * Sn + ss) * Hn + (cch - 2) * 128;

#pragma unroll 8
        for (int k = 0; k < 128; k += 4) {
            float4 hv = *(const float4*)(hrow + k);   // warp-uniform address
            acc += hv.x * Wt[k + 0][tag];
            acc += hv.y * Wt[k + 1][tag];
            acc += hv.z * Wt[k + 2][tag];
            acc += hv.w * Wt[k + 3][tag];
        }
    }
    g_feats[((size_t)(bb * Sn) + ss) * Tn + tag] = acc;
}

// ---------------- 5) Viterbi: one warp per batch ------------------------------
__global__ void k_viterbi(const float* __restrict__ trans, float* __restrict__ out)
{
    __shared__ float tr[32][32];              // tr[prev][next]
    __shared__ unsigned char bp[Sn][32];

    const int b   = blockIdx.x;
    const int tag = threadIdx.x;

    for (int p = 0; p < 32; p++) tr[p][tag] = trans[p * 32 + tag];
    __syncwarp();

    float v = (tag == 0) ? 0.f : -10000.f;
    const float* fb = g_feats + (size_t)b * Sn * Tn;

    for (int t = 0; t < Sn; t++) {
        float best = -3.4e38f; int arg = 0;
#pragma unroll
        for (int p = 0; p < 32; p++) {        // ascending + strict '>' = first argmax
            float vp = __shfl_sync(0xffffffffu, v, p);
            float sc = vp + tr[p][tag];
            if (sc > best) { best = sc; arg = p; }
        }
        bp[t][tag] = (unsigned char)arg;
        v = best + fb[t * 32 + tag];
    }

    float term = v + tr[0][tag];              // terminal uses trans[0, :]
    float best = -3.4e38f; int lt = 0;
#pragma unroll
    for (int p = 0; p < 32; p++) {
        float tp = __shfl_sync(0xffffffffu, term, p);
        if (tp > best) { best = tp; lt = p; }
    }
    __syncwarp();

    if (tag == 0) {
        int cur = lt;
        for (int t = Sn - 1; t >= 1; --t) {
            out[b * Sn + t] = (float)cur;
            cur = bp[t][cur];
        }
        out[b * Sn + 0] = (float)cur;
        out[NTOK + b]   = best;               // scores after the 64*256 paths
    }
}

// ---------------- launcher -----------------------------------------------------
extern "C" void kernel_launch(void* const* d_in, const int* in_sizes, int n_in,
                              void* d_out, int out_size)
{
    const int*   sent  = (const int*)  d_in[0];
    const float* embed = (const float*)d_in[1];
    const float* Wih_f = (const float*)d_in[2];
    const float* Whh_f = (const float*)d_in[3];
    const float* b_f   = (const float*)d_in[4];
    const float* Wih_b = (const float*)d_in[5];
    const float* Whh_b = (const float*)d_in[6];
    const float* b_b   = (const float*)d_in[7];
    const float* Wout  = (const float*)d_in[8];
    const float* bout  = (const float*)d_in[9];
    const float* trans = (const float*)d_in[10];
    float* out = (float*)d_out;
    (void)in_sizes; (void)n_in; (void)out_size;

    // 1) embedding
    k_embed<<<NTOK, 256>>>(sent, embed);

    // 2) input-side GEMMs (both directions), hoisted out of the recurrence
    dim3 gg(NTOK / 128, Gn / 128);
    k_gemm<<<gg, 256>>>(Wih_f, b_f, 0);
    k_gemm<<<gg, 256>>>(Wih_b, b_b, 1);

    // 3) persistent recurrent kernel (128 co-resident blocks + grid barrier)
    cudaFuncSetAttribute(k_lstm, cudaFuncAttributeMaxDynamicSharedMemorySize,
                         (int)SMEM_LSTM);
    k_lstm<<<128, 256, SMEM_LSTM>>>(Whh_f, Whh_b);

    // 4) emissions
    k_feats<<<NTOK / 8, 256>>>(Wout, bout);

    // 5) viterbi decode + writeback (paths as float, then scores)
    k_viterbi<<<Bn, 32>>>(trans, out);
}